// round 1
// baseline (speedup 1.0000x reference)
#include <cuda_runtime.h>

#define SEQ   49
#define CDIM  256
#define NHEAD 8
#define HD    32
#define NWIN  64
#define NB    2048
#define MROWS (NB * SEQ)          // 100352
#define QSCALE 0.17677669529663687f

typedef unsigned long long u64;

// Scratch (allocation-free rule: __device__ globals)
__device__ float g_q[(size_t)NB * NHEAD * SEQ * HD];
__device__ float g_k[(size_t)NB * NHEAD * SEQ * HD];
__device__ float g_v[(size_t)NB * NHEAD * SEQ * HD];
__device__ float g_att[(size_t)MROWS * CDIM];

__device__ __forceinline__ void fma2(u64 &acc, u64 a, u64 b) {
    asm("fma.rn.f32x2 %0, %1, %2, %0;" : "+l"(acc) : "l"(a), "l"(b));
}
__device__ __forceinline__ float2 unpack2(u64 v) {
    float2 f;
    asm("mov.b64 {%0, %1}, %2;" : "=f"(f.x), "=f"(f.y) : "l"(v));
    return f;
}

__device__ __forceinline__ void qkv_store(int row, int col, float v,
                                          const float* __restrict__ qkvb) {
    v += qkvb[col];
    const int which = col >> 8;        // 0=q 1=k 2=v
    const int c = col & 255;
    const int b = row / SEQ;
    const int n = row - b * SEQ;
    const int h = c >> 5, d = c & 31;
    const size_t off = ((size_t)((b * NHEAD + h) * SEQ + n)) * HD + d;
    if (which == 0)      g_q[off] = v * QSCALE;
    else if (which == 1) g_k[off] = v;
    else                 g_v[off] = v;
}

// 64x64 tile SGEMM, K=256, BK=16, 256 threads, 4x4 per thread.
// Accumulators are f32x2-packed pairs along M. B tile stored duplicated so
// the inner loop is pure LDS.128 + FFMA2 (no per-k packing movs).
// MODE 0: A = x, Ncols=768, scatter epilogue to g_q/g_k/g_v (+bias, q*scale)
// MODE 1: A = g_att, Ncols=256, Cout[row*256+col] = acc + bias[col]
template<int MODE, int NCOLS>
__global__ __launch_bounds__(256) void sgemm_kernel(
    const float* __restrict__ A, const float* __restrict__ Bw,
    const float* __restrict__ bias, float* __restrict__ Cout)
{
    __shared__ float As[16][68];        // [k][m], padded
    __shared__ float Bs[16][128];       // [k][2n] duplicated pairs

    const float* __restrict__ Aeff = (MODE == 1) ? (const float*)g_att : A;

    const int tid = threadIdx.x;
    const int tx = tid & 15, ty = tid >> 4;
    const int m0 = blockIdx.y * 64, n0 = blockIdx.x * 64;

    u64 acc[4][2] = {};

    const int arow = tid >> 2;            // 0..63
    const int akq  = (tid & 3) << 2;      // 0,4,8,12
    const int bkr  = tid >> 4;            // 0..15
    const int bnq  = (tid & 15) << 2;     // 0..60

    const float* Ap = Aeff + (size_t)(m0 + arow) * CDIM + akq;
    const float* Bp = Bw + (size_t)bkr * NCOLS + n0 + bnq;

    float4 a4 = *(const float4*)Ap;
    float4 b4 = *(const float4*)Bp;

    for (int kt = 0; kt < CDIM; kt += 16) {
        As[akq + 0][arow] = a4.x; As[akq + 1][arow] = a4.y;
        As[akq + 2][arow] = a4.z; As[akq + 3][arow] = a4.w;
        float* bd = &Bs[bkr][bnq << 1];
        bd[0] = b4.x; bd[1] = b4.x; bd[2] = b4.y; bd[3] = b4.y;
        bd[4] = b4.z; bd[5] = b4.z; bd[6] = b4.w; bd[7] = b4.w;
        __syncthreads();
        if (kt + 16 < CDIM) {            // prefetch next K-tile (hide LDG)
            a4 = *(const float4*)(Ap + kt + 16);
            b4 = *(const float4*)(Bp + (size_t)(kt + 16) * NCOLS);
        }
        #pragma unroll
        for (int k = 0; k < 16; k++) {
            ulonglong2 av = *(const ulonglong2*)&As[k][ty << 2];
            const ulonglong2* bp2 = (const ulonglong2*)&Bs[k][tx << 3];
            ulonglong2 b01 = bp2[0], b23 = bp2[1];
            fma2(acc[0][0], av.x, b01.x); fma2(acc[0][1], av.y, b01.x);
            fma2(acc[1][0], av.x, b01.y); fma2(acc[1][1], av.y, b01.y);
            fma2(acc[2][0], av.x, b23.x); fma2(acc[2][1], av.y, b23.x);
            fma2(acc[3][0], av.x, b23.y); fma2(acc[3][1], av.y, b23.y);
        }
        __syncthreads();
    }

    #pragma unroll
    for (int j = 0; j < 4; j++) {
        const int col = n0 + (tx << 2) + j;
        #pragma unroll
        for (int p = 0; p < 2; p++) {
            float2 f = unpack2(acc[j][p]);
            const int row = m0 + (ty << 2) + (p << 1);
            if (MODE == 0) {
                qkv_store(row,     col, f.x, bias);
                qkv_store(row + 1, col, f.y, bias);
            } else {
                Cout[(size_t)row * CDIM + col]       = f.x + bias[col];
                Cout[(size_t)(row + 1) * CDIM + col] = f.y + bias[col];
            }
        }
    }
}

// One block per (window b, head h). 64 threads; thread i < 49 owns query row i.
__global__ __launch_bounds__(64) void attn_kernel(
    const float* __restrict__ mask, const float* __restrict__ bias_table,
    const int* __restrict__ rel_index)
{
    __shared__ float ks[SEQ][HD];
    __shared__ float vs[SEQ][HD];
    __shared__ float bm[SEQ * SEQ];     // bias + mask, additive
    __shared__ float sc[SEQ][53];       // scores, odd-ish stride: conflict-free

    const int blk = blockIdx.x;         // b*8 + h
    const int b = blk >> 3, h = blk & 7;
    const int w = b & (NWIN - 1);       // window index for mask
    const int tid = threadIdx.x;

    const size_t base = (size_t)blk * SEQ * HD;
    const float4* k4 = (const float4*)(g_k + base);
    const float4* v4 = (const float4*)(g_v + base);
    float4* ks4 = (float4*)ks;
    float4* vs4 = (float4*)vs;
    for (int i = tid; i < SEQ * HD / 4; i += 64) { ks4[i] = k4[i]; vs4[i] = v4[i]; }
    const float* mrow = mask + (size_t)w * SEQ * SEQ;
    for (int i = tid; i < SEQ * SEQ; i += 64)
        bm[i] = bias_table[rel_index[i] * NHEAD + h] + mrow[i];
    __syncthreads();

    if (tid < SEQ) {
        const int i = tid;
        float q[HD];
        const float4* q4 = (const float4*)(g_q + base + (size_t)i * HD);
        #pragma unroll
        for (int t = 0; t < HD / 4; t++) {
            float4 xv = q4[t];
            q[4*t] = xv.x; q[4*t+1] = xv.y; q[4*t+2] = xv.z; q[4*t+3] = xv.w;
        }
        float mx = -1e30f;
        for (int j = 0; j < SEQ; j++) {
            float s = 0.f;
            const float4* kr = (const float4*)ks[j];
            #pragma unroll
            for (int t = 0; t < HD / 4; t++) {
                float4 kv = kr[t];
                s += q[4*t] * kv.x + q[4*t+1] * kv.y
                   + q[4*t+2] * kv.z + q[4*t+3] * kv.w;
            }
            s += bm[i * SEQ + j];
            sc[i][j] = s;
            mx = fmaxf(mx, s);
        }
        float sum = 0.f;
        for (int j = 0; j < SEQ; j++) {
            float e = __expf(sc[i][j] - mx);
            sc[i][j] = e;
            sum += e;
        }
        const float inv = 1.f / sum;
        float4 o[HD / 4] = {};
        for (int j = 0; j < SEQ; j++) {
            const float p = sc[i][j];
            const float4* vr = (const float4*)vs[j];
            #pragma unroll
            for (int t = 0; t < HD / 4; t++) {
                float4 vv = vr[t];
                o[t].x += p * vv.x; o[t].y += p * vv.y;
                o[t].z += p * vv.z; o[t].w += p * vv.w;
            }
        }
        // layout for proj GEMM: [b*49+i][h*32+d]  (matches transpose(0,2,1,3))
        float4* op = (float4*)(g_att + (size_t)(b * SEQ + i) * CDIM + h * HD);
        #pragma unroll
        for (int t = 0; t < HD / 4; t++) {
            float4 r;
            r.x = o[t].x * inv; r.y = o[t].y * inv;
            r.z = o[t].z * inv; r.w = o[t].w * inv;
            op[t] = r;
        }
    }
}

extern "C" void kernel_launch(void* const* d_in, const int* in_sizes, int n_in,
                              void* d_out, int out_size)
{
    const float* x          = (const float*)d_in[0];
    const float* mask       = (const float*)d_in[1];
    const float* qkv_w      = (const float*)d_in[2];
    const float* qkv_b      = (const float*)d_in[3];
    const float* proj_w     = (const float*)d_in[4];
    const float* proj_b     = (const float*)d_in[5];
    const float* bias_table = (const float*)d_in[6];
    const int*   rel_index  = (const int*)d_in[7];
    float* out = (float*)d_out;

    // 1) QKV projection -> g_q (pre-scaled), g_k, g_v in [B][H][N][hd]
    dim3 g1(768 / 64, MROWS / 64);
    sgemm_kernel<0, 768><<<g1, 256>>>(x, qkv_w, qkv_b, nullptr);

    // 2) windowed attention -> g_att in [B*N][C]
    attn_kernel<<<NB * NHEAD, 64>>>(mask, bias_table, rel_index);

    // 3) output projection -> d_out
    dim3 g3(CDIM / 64, MROWS / 64);
    sgemm_kernel<1, CDIM><<<g3, 256>>>(nullptr, proj_w, proj_b, out);
}

// round 4
// speedup vs baseline: 4.9963x; 4.9963x over previous
#include <cuda_runtime.h>
#include <cstdint>

#define SEQ   49
#define CDIM  256
#define NHEAD 8
#define HD    32
#define NWIN  64
#define NB    2048
#define MROWS (NB * SEQ)          // 100352
#define QSCALE 0.17677669529663687f

// ---------------- scratch (allocation-free rule) ----------------
__device__ float g_q[(size_t)NB * NHEAD * SEQ * HD];
__device__ float g_k[(size_t)NB * NHEAD * SEQ * HD];
__device__ float g_v[(size_t)NB * NHEAD * SEQ * HD];
__device__ float g_att[(size_t)MROWS * CDIM];
__device__ float g_xc[(size_t)MROWS * CDIM];     // x rounded to tf32 (rna)
__device__ float g_wT[768 * 256];                // qkv_w^T  [N][K], tf32-rounded
__device__ float g_pT[256 * 256];                // proj_w^T [N][K], tf32-rounded

__device__ __forceinline__ uint32_t smem_u32(const void* p) {
    uint32_t a;
    asm("{ .reg .u64 t; cvta.to.shared.u64 t, %1; cvt.u32.u64 %0, t; }" : "=r"(a) : "l"(p));
    return a;
}
__device__ __forceinline__ float to_tf32(float x) {
    uint32_t r; asm("cvt.rna.tf32.f32 %0, %1;" : "=r"(r) : "f"(x));
    return __uint_as_float(r);
}
#define CP_ASYNC16(s, g) \
    asm volatile("cp.async.cg.shared.global [%0], [%1], 16;" :: "r"(s), "l"(g) : "memory")

__device__ __forceinline__ void mma_tf32(float* c, const uint32_t* a, uint32_t b0, uint32_t b1) {
    asm volatile(
        "mma.sync.aligned.m16n8k8.row.col.f32.tf32.tf32.f32 "
        "{%0,%1,%2,%3}, {%4,%5,%6,%7}, {%8,%9}, {%0,%1,%2,%3};"
        : "+f"(c[0]), "+f"(c[1]), "+f"(c[2]), "+f"(c[3])
        : "r"(a[0]), "r"(a[1]), "r"(a[2]), "r"(a[3]), "r"(b0), "r"(b1));
}

// ---------------- tensor-core GEMM: C[M x N] = A[M x 256] * BT[N x 256]^T ----
// block 128x128, BK=32, 256 threads (8 warps: 4 along M x 2 along N).
// Warp tile 32x64 = 2 (m16) x 8 (n8) mma tiles. cp.async double buffer.
#define BM 128
#define BN 128
#define BK 32
#define LDSW 36                    // BK + 4 pad: conflict-free fragments
#define SM_BYTES (2 * (BM + BN) * LDSW * 4)   // 73728

__global__ __launch_bounds__(256) void mma_gemm(
    const float* __restrict__ A, const float* __restrict__ BT,
    const float* __restrict__ bias, float* __restrict__ Cout, int mode)
{
    extern __shared__ float sm[];
    const uint32_t sbase = smem_u32(sm);
    float* As = sm;                          // [2][BM][LDSW]
    float* Bs = sm + 2 * BM * LDSW;          // [2][BN][LDSW]

    const int tid = threadIdx.x;
    const int wid = tid >> 5, lane = tid & 31;
    const int wm = wid & 3, wn = wid >> 2;
    const int gid = lane >> 2, tig = lane & 3;
    const int m0 = blockIdx.y * BM, n0 = blockIdx.x * BN;

    float acc[2][8][4];
    #pragma unroll
    for (int i = 0; i < 2; i++)
        #pragma unroll
        for (int j = 0; j < 8; j++)
            acc[i][j][0] = acc[i][j][1] = acc[i][j][2] = acc[i][j][3] = 0.f;

    const float* Ag = A + (size_t)m0 * CDIM;
    const float* Bg = BT + (size_t)n0 * CDIM;

    const int ldr = tid >> 3;                // 0..31 (x4 iters -> 128 rows)
    const int ldq = tid & 7;                 // 16B chunk within 128B row

    // chunk loader: A and B tiles, 4+4 cp.async per thread
    #define LOAD_CHUNK(cc, buf) do {                                              \
        const uint32_t abase = sbase + ((buf) * BM * LDSW) * 4;                   \
        const uint32_t bbase = sbase + (2 * BM * LDSW + (buf) * BN * LDSW) * 4;   \
        _Pragma("unroll")                                                         \
        for (int i = 0; i < 4; i++) {                                             \
            int r = ldr + i * 32;                                                 \
            CP_ASYNC16(abase + (r * LDSW + ldq * 4) * 4,                          \
                       Ag + (size_t)r * CDIM + (cc) * BK + ldq * 4);              \
            CP_ASYNC16(bbase + (r * LDSW + ldq * 4) * 4,                          \
                       Bg + (size_t)r * CDIM + (cc) * BK + ldq * 4);              \
        }                                                                         \
        asm volatile("cp.async.commit_group;");                                   \
    } while (0)

    LOAD_CHUNK(0, 0);

    #pragma unroll 1
    for (int c = 0; c < CDIM / BK; c++) {
        const int buf = c & 1;
        if (c + 1 < CDIM / BK) {
            LOAD_CHUNK(c + 1, buf ^ 1);
            asm volatile("cp.async.wait_group 1;" ::: "memory");
        } else {
            asm volatile("cp.async.wait_group 0;" ::: "memory");
        }
        __syncthreads();

        const float* sa = As + buf * BM * LDSW + (wm * 32) * LDSW;
        const float* sb = Bs + buf * BN * LDSW + (wn * 64) * LDSW;
        #pragma unroll
        for (int ks = 0; ks < 4; ks++) {
            const int k = ks * 8;
            uint32_t a[2][4];
            #pragma unroll
            for (int mt = 0; mt < 2; mt++) {
                const float* ap = sa + (mt * 16 + gid) * LDSW + k + tig;
                a[mt][0] = __float_as_uint(ap[0]);
                a[mt][1] = __float_as_uint(ap[8 * LDSW]);
                a[mt][2] = __float_as_uint(ap[4]);
                a[mt][3] = __float_as_uint(ap[8 * LDSW + 4]);
            }
            #pragma unroll
            for (int nt = 0; nt < 8; nt++) {
                const float* bp = sb + (nt * 8 + gid) * LDSW + k + tig;
                uint32_t b0 = __float_as_uint(bp[0]);
                uint32_t b1 = __float_as_uint(bp[4]);
                mma_tf32(acc[0][nt], a[0], b0, b1);
                mma_tf32(acc[1][nt], a[1], b0, b1);
            }
        }
        __syncthreads();
    }

    // epilogue: thread owns C[row(+8)][col..col+1] per tile
    #pragma unroll
    for (int mt = 0; mt < 2; mt++) {
        #pragma unroll
        for (int nt = 0; nt < 8; nt++) {
            const int row = m0 + wm * 32 + mt * 16 + gid;
            const int col = n0 + wn * 64 + nt * 8 + tig * 2;
            const float b0 = __ldg(bias + col), b1 = __ldg(bias + col + 1);
            float2 lo = make_float2(acc[mt][nt][0] + b0, acc[mt][nt][1] + b1);
            float2 hi = make_float2(acc[mt][nt][2] + b0, acc[mt][nt][3] + b1);
            if (mode == 0) {
                const int which = col >> 8;           // 0=q 1=k 2=v
                float* dbuf = which == 0 ? g_q : (which == 1 ? g_k : g_v);
                if (which == 0) {
                    lo.x *= QSCALE; lo.y *= QSCALE; hi.x *= QSCALE; hi.y *= QSCALE;
                }
                const int cc = col & 255, h = cc >> 5, d = cc & 31;
                {
                    const int b = row / SEQ, n = row - b * SEQ;
                    *(float2*)(dbuf + ((size_t)((b * NHEAD + h) * SEQ + n)) * HD + d) = lo;
                }
                {
                    const int r2 = row + 8;
                    const int b = r2 / SEQ, n = r2 - b * SEQ;
                    *(float2*)(dbuf + ((size_t)((b * NHEAD + h) * SEQ + n)) * HD + d) = hi;
                }
            } else {
                *(float2*)(Cout + (size_t)row * CDIM + col) = lo;
                *(float2*)(Cout + (size_t)(row + 8) * CDIM + col) = hi;
            }
        }
    }
}

// ---------------- weight transpose (+ tf32 round): dst[N][K] = src[K][N] ----
__global__ void transpose_kernel(const float* __restrict__ src, float* __restrict__ dst,
                                 int R, int C)   // src is [R][C]
{
    __shared__ float t[32][33];
    const int bx = blockIdx.x * 32, by = blockIdx.y * 32;
    const int tx = threadIdx.x, ty = threadIdx.y;
    #pragma unroll
    for (int j = 0; j < 32; j += 8)
        t[ty + j][tx] = src[(size_t)(by + ty + j) * C + bx + tx];
    __syncthreads();
    #pragma unroll
    for (int j = 0; j < 32; j += 8)
        dst[(size_t)(bx + ty + j) * R + by + tx] = to_tf32(t[tx][ty + j]);
}

__global__ void cvt_tf32_kernel(const float4* __restrict__ s, float4* __restrict__ d, int n4)
{
    int i = blockIdx.x * blockDim.x + threadIdx.x;
    if (i < n4) {
        float4 v = s[i];
        v.x = to_tf32(v.x); v.y = to_tf32(v.y); v.z = to_tf32(v.z); v.w = to_tf32(v.w);
        d[i] = v;
    }
}

// ---------------- attention (per window x head), fp32 ----------------
__global__ __launch_bounds__(64) void attn_kernel(
    const float* __restrict__ mask, const float* __restrict__ bias_table,
    const int* __restrict__ rel_index)
{
    __shared__ float ks[SEQ][HD];
    __shared__ float vs[SEQ][HD];
    __shared__ float bm[SEQ * SEQ];
    __shared__ float sc[SEQ][53];

    const int blk = blockIdx.x;
    const int b = blk >> 3, h = blk & 7;
    const int w = b & (NWIN - 1);
    const int tid = threadIdx.x;

    const size_t base = (size_t)blk * SEQ * HD;
    const float4* k4 = (const float4*)(g_k + base);
    const float4* v4 = (const float4*)(g_v + base);
    float4* ks4 = (float4*)ks;
    float4* vs4 = (float4*)vs;
    for (int i = tid; i < SEQ * HD / 4; i += 64) { ks4[i] = k4[i]; vs4[i] = v4[i]; }
    const float* mrow = mask + (size_t)w * SEQ * SEQ;
    for (int i = tid; i < SEQ * SEQ; i += 64)
        bm[i] = bias_table[rel_index[i] * NHEAD + h] + mrow[i];
    __syncthreads();

    if (tid < SEQ) {
        const int i = tid;
        float q[HD];
        const float4* q4 = (const float4*)(g_q + base + (size_t)i * HD);
        #pragma unroll
        for (int t = 0; t < HD / 4; t++) {
            float4 xv = q4[t];
            q[4*t] = xv.x; q[4*t+1] = xv.y; q[4*t+2] = xv.z; q[4*t+3] = xv.w;
        }
        float mx = -1e30f;
        for (int j = 0; j < SEQ; j++) {
            float s = 0.f;
            const float4* kr = (const float4*)ks[j];
            #pragma unroll
            for (int t = 0; t < HD / 4; t++) {
                float4 kv = kr[t];
                s += q[4*t] * kv.x + q[4*t+1] * kv.y + q[4*t+2] * kv.z + q[4*t+3] * kv.w;
            }
            s += bm[i * SEQ + j];
            sc[i][j] = s;
            mx = fmaxf(mx, s);
        }
        float sum = 0.f;
        for (int j = 0; j < SEQ; j++) {
            float e = __expf(sc[i][j] - mx);
            sc[i][j] = e;
            sum += e;
        }
        const float inv = 1.f / sum;
        float4 o[HD / 4] = {};
        for (int j = 0; j < SEQ; j++) {
            const float p = sc[i][j];
            const float4* vr = (const float4*)vs[j];
            #pragma unroll
            for (int t = 0; t < HD / 4; t++) {
                float4 vv = vr[t];
                o[t].x += p * vv.x; o[t].y += p * vv.y;
                o[t].z += p * vv.z; o[t].w += p * vv.w;
            }
        }
        float4* op = (float4*)(g_att + (size_t)(b * SEQ + i) * CDIM + h * HD);
        #pragma unroll
        for (int t = 0; t < HD / 4; t++) {
            float4 r;   // tf32-rounded so the proj MMA truncation is exact
            r.x = to_tf32(o[t].x * inv); r.y = to_tf32(o[t].y * inv);
            r.z = to_tf32(o[t].z * inv); r.w = to_tf32(o[t].w * inv);
            op[t] = r;
        }
    }
}

// ---------------- launch ----------------
extern "C" void kernel_launch(void* const* d_in, const int* in_sizes, int n_in,
                              void* d_out, int out_size)
{
    const float* x          = (const float*)d_in[0];
    const float* mask       = (const float*)d_in[1];
    const float* qkv_w      = (const float*)d_in[2];
    const float* qkv_b      = (const float*)d_in[3];
    const float* proj_w     = (const float*)d_in[4];
    const float* proj_b     = (const float*)d_in[5];
    const float* bias_table = (const float*)d_in[6];
    const int*   rel_index  = (const int*)d_in[7];
    float* out = (float*)d_out;

    float *p_att, *p_wT, *p_pT, *p_xc;
    cudaGetSymbolAddress((void**)&p_att, g_att);
    cudaGetSymbolAddress((void**)&p_wT,  g_wT);
    cudaGetSymbolAddress((void**)&p_pT,  g_pT);
    cudaGetSymbolAddress((void**)&p_xc,  g_xc);

    cudaFuncSetAttribute(mma_gemm, cudaFuncAttributeMaxDynamicSharedMemorySize, SM_BYTES);

    // 0) round x to tf32 (unbiased rna); transpose+round weights to K-major
    const int n4 = MROWS * CDIM / 4;
    cvt_tf32_kernel<<<(n4 + 255) / 256, 256>>>((const float4*)x, (float4*)p_xc, n4);
    transpose_kernel<<<dim3(768 / 32, 256 / 32), dim3(32, 8)>>>(qkv_w, p_wT, 256, 768);
    transpose_kernel<<<dim3(256 / 32, 256 / 32), dim3(32, 8)>>>(proj_w, p_pT, 256, 256);

    // 1) QKV projection (tensor cores) -> g_q (scaled) / g_k / g_v
    mma_gemm<<<dim3(768 / BN, MROWS / BM), 256, SM_BYTES>>>(p_xc, p_wT, qkv_b, nullptr, 0);

    // 2) windowed attention -> g_att
    attn_kernel<<<NB * NHEAD, 64>>>(mask, bias_table, rel_index);

    // 3) output projection -> d_out
    mma_gemm<<<dim3(CDIM / BN, MROWS / BM), 256, SM_BYTES>>>(p_att, p_pT, proj_b, out, 1);
}

// round 6
// speedup vs baseline: 5.5669x; 1.1142x over previous
#include <cuda_runtime.h>
#include <cstdint>

#define SEQ   49
#define CDIM  256
#define NHEAD 8
#define HD    32
#define NWIN  64
#define NB    2048
#define MROWS (NB * SEQ)          // 100352
#define QSCALE 0.17677669529663687f

// ---------------- scratch (allocation-free rule) ----------------
__device__ float g_q[(size_t)NB * NHEAD * SEQ * HD];
__device__ float g_k[(size_t)NB * NHEAD * SEQ * HD];
__device__ float g_v[(size_t)NB * NHEAD * SEQ * HD];
__device__ float g_att[(size_t)MROWS * CDIM];
__device__ float g_xc[(size_t)MROWS * CDIM];     // x rounded to tf32 (rna)
__device__ float g_wT[768 * 256];                // qkv_w^T  [N][K], tf32-rounded
__device__ float g_pT[256 * 256];                // proj_w^T [N][K], tf32-rounded
__device__ float g_bm[NWIN * NHEAD * SEQ * SEQ]; // bias+mask, precombined (4.9MB)

__device__ __forceinline__ uint32_t smem_u32(const void* p) {
    uint32_t a;
    asm("{ .reg .u64 t; cvta.to.shared.u64 t, %1; cvt.u32.u64 %0, t; }" : "=r"(a) : "l"(p));
    return a;
}
__device__ __forceinline__ float to_tf32(float x) {
    uint32_t r; asm("cvt.rna.tf32.f32 %0, %1;" : "=r"(r) : "f"(x));
    return __uint_as_float(r);
}
#define CP_ASYNC16(s, g) \
    asm volatile("cp.async.cg.shared.global [%0], [%1], 16;" :: "r"(s), "l"(g) : "memory")

__device__ __forceinline__ void mma_tf32(float* c, const uint32_t* a, uint32_t b0, uint32_t b1) {
    asm volatile(
        "mma.sync.aligned.m16n8k8.row.col.f32.tf32.tf32.f32 "
        "{%0,%1,%2,%3}, {%4,%5,%6,%7}, {%8,%9}, {%0,%1,%2,%3};"
        : "+f"(c[0]), "+f"(c[1]), "+f"(c[2]), "+f"(c[3])
        : "r"(a[0]), "r"(a[1]), "r"(a[2]), "r"(a[3]), "r"(b0), "r"(b1));
}

// ---------------- tensor-core GEMM: C[M x N] = A[M x 256] * BT[N x 256]^T ----
// block 128x128, BK=32, 128 threads = 4 warps (2Mx2N), warp tile 64x64.
// Per k-step: 32 LDS : 32 MMA (1:1). Double-buffered cp.async. 2 CTAs/SM.
#define BM 128
#define BN 128
#define BK 32
#define LDSW 36                    // BK + 4 pad: conflict-free fragments
#define SM_BYTES (2 * (BM + BN) * LDSW * 4)   // 73728

__global__ __launch_bounds__(128) void mma_gemm(
    const float* __restrict__ A, const float* __restrict__ BT,
    const float* __restrict__ bias, float* __restrict__ Cout, int mode)
{
    extern __shared__ float sm[];
    const uint32_t sbase = smem_u32(sm);
    float* As = sm;                          // [2][BM][LDSW]
    float* Bs = sm + 2 * BM * LDSW;          // [2][BN][LDSW]

    const int tid = threadIdx.x;
    const int wid = tid >> 5, lane = tid & 31;
    const int wm = wid & 1, wn = wid >> 1;
    const int gid = lane >> 2, tig = lane & 3;
    const int m0 = blockIdx.y * BM, n0 = blockIdx.x * BN;

    float acc[4][8][4];
    #pragma unroll
    for (int i = 0; i < 4; i++)
        #pragma unroll
        for (int j = 0; j < 8; j++)
            acc[i][j][0] = acc[i][j][1] = acc[i][j][2] = acc[i][j][3] = 0.f;

    const float* Ag = A + (size_t)m0 * CDIM;
    const float* Bg = BT + (size_t)n0 * CDIM;

    const int ldr = tid >> 3;                // 0..15 (x8 iters -> 128 rows)
    const int ldq = tid & 7;                 // 16B chunk within 128B row

    // chunk loader: A and B tiles, 8+8 cp.async per thread
    #define LOAD_CHUNK(cc, buf) do {                                              \
        const uint32_t abase = sbase + ((buf) * BM * LDSW) * 4;                   \
        const uint32_t bbase = sbase + (2 * BM * LDSW + (buf) * BN * LDSW) * 4;   \
        _Pragma("unroll")                                                         \
        for (int i = 0; i < 8; i++) {                                             \
            int r = ldr + i * 16;                                                 \
            CP_ASYNC16(abase + (r * LDSW + ldq * 4) * 4,                          \
                       Ag + (size_t)r * CDIM + (cc) * BK + ldq * 4);              \
            CP_ASYNC16(bbase + (r * LDSW + ldq * 4) * 4,                          \
                       Bg + (size_t)r * CDIM + (cc) * BK + ldq * 4);              \
        }                                                                         \
        asm volatile("cp.async.commit_group;");                                   \
    } while (0)

    LOAD_CHUNK(0, 0);

    #pragma unroll 1
    for (int c = 0; c < CDIM / BK; c++) {
        const int buf = c & 1;
        if (c + 1 < CDIM / BK) {
            LOAD_CHUNK(c + 1, buf ^ 1);
            asm volatile("cp.async.wait_group 1;" ::: "memory");
        } else {
            asm volatile("cp.async.wait_group 0;" ::: "memory");
        }
        __syncthreads();

        const float* sa = As + buf * BM * LDSW + (wm * 64) * LDSW;
        const float* sb = Bs + buf * BN * LDSW + (wn * 64) * LDSW;
        #pragma unroll
        for (int ks = 0; ks < 4; ks++) {
            const int k = ks * 8;
            uint32_t a[4][4];
            #pragma unroll
            for (int mt = 0; mt < 4; mt++) {
                const float* ap = sa + (mt * 16 + gid) * LDSW + k + tig;
                a[mt][0] = __float_as_uint(ap[0]);
                a[mt][1] = __float_as_uint(ap[8 * LDSW]);
                a[mt][2] = __float_as_uint(ap[4]);
                a[mt][3] = __float_as_uint(ap[8 * LDSW + 4]);
            }
            #pragma unroll
            for (int nt = 0; nt < 8; nt++) {
                const float* bp = sb + (nt * 8 + gid) * LDSW + k + tig;
                uint32_t b0 = __float_as_uint(bp[0]);
                uint32_t b1 = __float_as_uint(bp[4]);
                #pragma unroll
                for (int mt = 0; mt < 4; mt++)
                    mma_tf32(acc[mt][nt], a[mt], b0, b1);
            }
        }
        __syncthreads();
    }

    // epilogue: thread owns C[row(+8)][col..col+1] per tile
    #pragma unroll
    for (int mt = 0; mt < 4; mt++) {
        #pragma unroll
        for (int nt = 0; nt < 8; nt++) {
            const int row = m0 + wm * 64 + mt * 16 + gid;
            const int col = n0 + wn * 64 + nt * 8 + tig * 2;
            const float b0 = __ldg(bias + col), b1 = __ldg(bias + col + 1);
            float2 lo = make_float2(acc[mt][nt][0] + b0, acc[mt][nt][1] + b1);
            float2 hi = make_float2(acc[mt][nt][2] + b0, acc[mt][nt][3] + b1);
            if (mode == 0) {
                const int which = col >> 8;           // 0=q 1=k 2=v
                float* dbuf = which == 0 ? g_q : (which == 1 ? g_k : g_v);
                if (which == 0) {
                    lo.x *= QSCALE; lo.y *= QSCALE; hi.x *= QSCALE; hi.y *= QSCALE;
                }
                const int cc = col & 255, h = cc >> 5, d = cc & 31;
                {
                    const int b = row / SEQ, n = row - b * SEQ;
                    *(float2*)(dbuf + ((size_t)((b * NHEAD + h) * SEQ + n)) * HD + d) = lo;
                }
                {
                    const int r2 = row + 8;
                    const int b = r2 / SEQ, n = r2 - b * SEQ;
                    *(float2*)(dbuf + ((size_t)((b * NHEAD + h) * SEQ + n)) * HD + d) = hi;
                }
            } else {
                *(float2*)(Cout + (size_t)row * CDIM + col) = lo;
                *(float2*)(Cout + (size_t)(row + 8) * CDIM + col) = hi;
            }
        }
    }
}

// ---------------- weight transpose (+ tf32 round): dst[N][K] = src[K][N] ----
__global__ void transpose_kernel(const float* __restrict__ src, float* __restrict__ dst,
                                 int R, int C)   // src is [R][C]
{
    __shared__ float t[32][33];
    const int bx = blockIdx.x * 32, by = blockIdx.y * 32;
    const int tx = threadIdx.x, ty = threadIdx.y;
    #pragma unroll
    for (int j = 0; j < 32; j += 8)
        t[ty + j][tx] = src[(size_t)(by + ty + j) * C + bx + tx];
    __syncthreads();
    #pragma unroll
    for (int j = 0; j < 32; j += 8)
        dst[(size_t)(bx + ty + j) * R + by + tx] = to_tf32(t[tx][ty + j]);
}

__global__ void cvt_tf32_kernel(const float4* __restrict__ s, float4* __restrict__ d, int n4)
{
    int i = blockIdx.x * blockDim.x + threadIdx.x;
    if (i < n4) {
        float4 v = s[i];
        v.x = to_tf32(v.x); v.y = to_tf32(v.y); v.z = to_tf32(v.z); v.w = to_tf32(v.w);
        d[i] = v;
    }
}

// ---------------- precombine bias gather + mask: g_bm[w][h][49*49] ----------
__global__ void bm_kernel(const float* __restrict__ mask,
                          const float* __restrict__ bias_table,
                          const int* __restrict__ rel_index)
{
    const int w = blockIdx.x >> 3, h = blockIdx.x & 7;
    const float* mrow = mask + (size_t)w * SEQ * SEQ;
    float* dst = g_bm + (size_t)blockIdx.x * SEQ * SEQ;
    for (int i = threadIdx.x; i < SEQ * SEQ; i += blockDim.x)
        dst[i] = bias_table[rel_index[i] * NHEAD + h] + mrow[i];
}

// ---------------- attention (per window x head), fp32 ----------------
__global__ __launch_bounds__(64) void attn_kernel()
{
    __shared__ float ks[SEQ][HD];
    __shared__ float vs[SEQ][HD];
    __shared__ float bm[SEQ * SEQ];
    __shared__ float sc[SEQ][53];

    const int blk = blockIdx.x;
    const int b = blk >> 3, h = blk & 7;
    const int w = b & (NWIN - 1);
    const int tid = threadIdx.x;

    const size_t base = (size_t)blk * SEQ * HD;
    const float4* k4 = (const float4*)(g_k + base);
    const float4* v4 = (const float4*)(g_v + base);
    float4* ks4 = (float4*)ks;
    float4* vs4 = (float4*)vs;
    for (int i = tid; i < SEQ * HD / 4; i += 64) { ks4[i] = k4[i]; vs4[i] = v4[i]; }
    const float* bmg = g_bm + (size_t)(w * NHEAD + h) * SEQ * SEQ;
    for (int i = tid; i < SEQ * SEQ; i += 64)
        bm[i] = bmg[i];                      // coalesced, L2-resident
    __syncthreads();

    if (tid < SEQ) {
        const int i = tid;
        float q[HD];
        const float4* q4 = (const float4*)(g_q + base + (size_t)i * HD);
        #pragma unroll
        for (int t = 0; t < HD / 4; t++) {
            float4 xv = q4[t];
            q[4*t] = xv.x; q[4*t+1] = xv.y; q[4*t+2] = xv.z; q[4*t+3] = xv.w;
        }
        float mx = -1e30f;
        for (int j = 0; j < SEQ; j++) {
            float s = 0.f;
            const float4* kr = (const float4*)ks[j];
            #pragma unroll
            for (int t = 0; t < HD / 4; t++) {
                float4 kv = kr[t];
                s += q[4*t] * kv.x + q[4*t+1] * kv.y + q[4*t+2] * kv.z + q[4*t+3] * kv.w;
            }
            s += bm[i * SEQ + j];
            sc[i][j] = s;
            mx = fmaxf(mx, s);
        }
        float sum = 0.f;
        for (int j = 0; j < SEQ; j++) {
            float e = __expf(sc[i][j] - mx);
            sc[i][j] = e;
            sum += e;
        }
        const float inv = 1.f / sum;
        float4 o[HD / 4] = {};
        for (int j = 0; j < SEQ; j++) {
            const float p = sc[i][j];
            const float4* vr = (const float4*)vs[j];
            #pragma unroll
            for (int t = 0; t < HD / 4; t++) {
                float4 vv = vr[t];
                o[t].x += p * vv.x; o[t].y += p * vv.y;
                o[t].z += p * vv.z; o[t].w += p * vv.w;
            }
        }
        float4* op = (float4*)(g_att + (size_t)(b * SEQ + i) * CDIM + h * HD);
        #pragma unroll
        for (int t = 0; t < HD / 4; t++) {
            float4 r;   // tf32-rounded so the proj MMA truncation is exact
            r.x = to_tf32(o[t].x * inv); r.y = to_tf32(o[t].y * inv);
            r.z = to_tf32(o[t].z * inv); r.w = to_tf32(o[t].w * inv);
            op[t] = r;
        }
    }
}

// ---------------- launch ----------------
extern "C" void kernel_launch(void* const* d_in, const int* in_sizes, int n_in,
                              void* d_out, int out_size)
{
    const float* x          = (const float*)d_in[0];
    const float* mask       = (const float*)d_in[1];
    const float* qkv_w      = (const float*)d_in[2];
    const float* qkv_b      = (const float*)d_in[3];
    const float* proj_w     = (const float*)d_in[4];
    const float* proj_b     = (const float*)d_in[5];
    const float* bias_table = (const float*)d_in[6];
    const int*   rel_index  = (const int*)d_in[7];
    float* out = (float*)d_out;

    float *p_att, *p_wT, *p_pT, *p_xc;
    cudaGetSymbolAddress((void**)&p_att, g_att);
    cudaGetSymbolAddress((void**)&p_wT,  g_wT);
    cudaGetSymbolAddress((void**)&p_pT,  g_pT);
    cudaGetSymbolAddress((void**)&p_xc,  g_xc);

    cudaFuncSetAttribute(mma_gemm, cudaFuncAttributeMaxDynamicSharedMemorySize, SM_BYTES);

    // 0) round x to tf32 (unbiased rna); transpose+round weights; combine bias+mask
    const int n4 = MROWS * CDIM / 4;
    cvt_tf32_kernel<<<(n4 + 255) / 256, 256>>>((const float4*)x, (float4*)p_xc, n4);
    transpose_kernel<<<dim3(768 / 32, 256 / 32), dim3(32, 8)>>>(qkv_w, p_wT, 256, 768);
    transpose_kernel<<<dim3(256 / 32, 256 / 32), dim3(32, 8)>>>(proj_w, p_pT, 256, 256);
    bm_kernel<<<NWIN * NHEAD, 256>>>(mask, bias_table, rel_index);

    // 1) QKV projection (tensor cores) -> g_q (scaled) / g_k / g_v
    mma_gemm<<<dim3(768 / BN, MROWS / BM), 128, SM_BYTES>>>(p_xc, p_wT, qkv_b, nullptr, 0);

    // 2) windowed attention -> g_att
    attn_kernel<<<NB * NHEAD, 64>>>();

    // 3) output projection -> d_out
    mma_gemm<<<dim3(CDIM / BN, MROWS / BM), 128, SM_BYTES>>>(p_att, p_pT, proj_b, out, 1);
}